// round 5
// baseline (speedup 1.0000x reference)
#include <cuda_runtime.h>
#include <math.h>

// Problem constants
#define B_   8
#define C_   256
#define SQ_  4096   // 64*64 query pixels
#define SK_  1024   // 32*32 kv pixels
#define NH_  8
#define D_   32
#define NP_  4
#define OC_  64     // offset conv out channels = NH*NP*2
#define KC_  2304   // C_*9 im2col depth

// Scratch (device globals — no allocation allowed)
__device__ float g_q  [B_ * SQ_ * C_];   // (b, s, c)  channel-last
__device__ float g_k  [B_ * SK_ * C_];   // (b, sk, c)
__device__ float g_v  [B_ * SK_ * C_];   // (b, sk, c)
__device__ float g_off[B_ * SQ_ * OC_];  // (b, s, oc) -> final sample coords (kv pixel space)
__device__ float g_att[B_ * SQ_ * C_];   // (b, s, c)

// ---------------------------------------------------------------------------
// Q projection: g_q[b][s][o] = sum_c q_w[o][c] * X[b][c][s]
// 64x64 tile, 16x16 threads, 4x4 microtile, k-major weight smem tile:
// mainloop = 2x LDS.128 + 16 FFMA per k-step.
// ---------------------------------------------------------------------------
__global__ __launch_bounds__(256)
void gemm_q_kernel(const float* __restrict__ X, const float* __restrict__ W) {
    int b  = blockIdx.z;
    int o0 = blockIdx.y * 64;
    int s0 = blockIdx.x * 64;
    int tx = threadIdx.x;          // 0..15 -> s
    int ty = threadIdx.y;          // 0..15 -> o
    int tid = ty * 16 + tx;

    __shared__ float Xs[16][64];   // [k][s]
    __shared__ float Wt[16][68];   // [k][o]  (k-major, pad 68 keeps float4 align)

    float acc[4][4];
#pragma unroll
    for (int i = 0; i < 4; i++)
#pragma unroll
        for (int j = 0; j < 4; j++) acc[i][j] = 0.f;

    for (int kc = 0; kc < C_; kc += 16) {
        {   // load X tile: 16k x 64s, float4 per thread
            int kk = tid >> 4;
            int sc = (tid & 15) * 4;
            float4 xv = *reinterpret_cast<const float4*>(
                X + ((size_t)(b * C_ + kc + kk)) * SQ_ + s0 + sc);
            *reinterpret_cast<float4*>(&Xs[kk][sc]) = xv;
        }
        {   // load W tile (o-major in gmem) and transpose into k-major smem
            int row = tid >> 2;            // o: 0..63
            int col = (tid & 3) * 4;       // k: 0,4,8,12
            float4 wv = *reinterpret_cast<const float4*>(
                W + (size_t)(o0 + row) * C_ + kc + col);
            Wt[col + 0][row] = wv.x;
            Wt[col + 1][row] = wv.y;
            Wt[col + 2][row] = wv.z;
            Wt[col + 3][row] = wv.w;
        }
        __syncthreads();
#pragma unroll
        for (int kk = 0; kk < 16; kk++) {
            float4 xv = *reinterpret_cast<const float4*>(&Xs[kk][tx * 4]);
            float4 wv = *reinterpret_cast<const float4*>(&Wt[kk][ty * 4]);
            acc[0][0] += xv.x * wv.x; acc[0][1] += xv.x * wv.y; acc[0][2] += xv.x * wv.z; acc[0][3] += xv.x * wv.w;
            acc[1][0] += xv.y * wv.x; acc[1][1] += xv.y * wv.y; acc[1][2] += xv.y * wv.z; acc[1][3] += xv.y * wv.w;
            acc[2][0] += xv.z * wv.x; acc[2][1] += xv.z * wv.y; acc[2][2] += xv.z * wv.z; acc[2][3] += xv.z * wv.w;
            acc[3][0] += xv.w * wv.x; acc[3][1] += xv.w * wv.y; acc[3][2] += xv.w * wv.z; acc[3][3] += xv.w * wv.w;
        }
        __syncthreads();
    }
#pragma unroll
    for (int i = 0; i < 4; i++) {
        float4 o4 = make_float4(acc[i][0], acc[i][1], acc[i][2], acc[i][3]);
        *reinterpret_cast<float4*>(
            g_q + ((size_t)b * SQ_ + s0 + tx * 4 + i) * C_ + o0 + ty * 4) = o4;
    }
}

// ---------------------------------------------------------------------------
// Fused K+V projection: one X tile in smem, two k-major weight tiles.
// ---------------------------------------------------------------------------
__global__ __launch_bounds__(256)
void gemm_kv_kernel(const float* __restrict__ X,
                    const float* __restrict__ Wk_g,
                    const float* __restrict__ Wv_g) {
    int b  = blockIdx.z;
    int o0 = blockIdx.y * 64;
    int s0 = blockIdx.x * 64;
    int tx = threadIdx.x;
    int ty = threadIdx.y;
    int tid = ty * 16 + tx;

    __shared__ float Xs[16][64];
    __shared__ float Wkt[16][68];
    __shared__ float Wvt[16][68];

    float acck[4][4], accv[4][4];
#pragma unroll
    for (int i = 0; i < 4; i++)
#pragma unroll
        for (int j = 0; j < 4; j++) { acck[i][j] = 0.f; accv[i][j] = 0.f; }

    for (int kc = 0; kc < C_; kc += 16) {
        {
            int kk = tid >> 4;
            int sc = (tid & 15) * 4;
            float4 xv = *reinterpret_cast<const float4*>(
                X + ((size_t)(b * C_ + kc + kk)) * SK_ + s0 + sc);
            *reinterpret_cast<float4*>(&Xs[kk][sc]) = xv;
        }
        {
            int row = tid >> 2;
            int col = (tid & 3) * 4;
            size_t woff = (size_t)(o0 + row) * C_ + kc + col;
            float4 wk = *reinterpret_cast<const float4*>(Wk_g + woff);
            float4 wv = *reinterpret_cast<const float4*>(Wv_g + woff);
            Wkt[col + 0][row] = wk.x; Wkt[col + 1][row] = wk.y;
            Wkt[col + 2][row] = wk.z; Wkt[col + 3][row] = wk.w;
            Wvt[col + 0][row] = wv.x; Wvt[col + 1][row] = wv.y;
            Wvt[col + 2][row] = wv.z; Wvt[col + 3][row] = wv.w;
        }
        __syncthreads();
#pragma unroll
        for (int kk = 0; kk < 16; kk++) {
            float4 xv = *reinterpret_cast<const float4*>(&Xs[kk][tx * 4]);
            float4 kv4 = *reinterpret_cast<const float4*>(&Wkt[kk][ty * 4]);
            acck[0][0] += xv.x * kv4.x; acck[0][1] += xv.x * kv4.y; acck[0][2] += xv.x * kv4.z; acck[0][3] += xv.x * kv4.w;
            acck[1][0] += xv.y * kv4.x; acck[1][1] += xv.y * kv4.y; acck[1][2] += xv.y * kv4.z; acck[1][3] += xv.y * kv4.w;
            acck[2][0] += xv.z * kv4.x; acck[2][1] += xv.z * kv4.y; acck[2][2] += xv.z * kv4.z; acck[2][3] += xv.z * kv4.w;
            acck[3][0] += xv.w * kv4.x; acck[3][1] += xv.w * kv4.y; acck[3][2] += xv.w * kv4.z; acck[3][3] += xv.w * kv4.w;
            float4 vv4 = *reinterpret_cast<const float4*>(&Wvt[kk][ty * 4]);
            accv[0][0] += xv.x * vv4.x; accv[0][1] += xv.x * vv4.y; accv[0][2] += xv.x * vv4.z; accv[0][3] += xv.x * vv4.w;
            accv[1][0] += xv.y * vv4.x; accv[1][1] += xv.y * vv4.y; accv[1][2] += xv.y * vv4.z; accv[1][3] += xv.y * vv4.w;
            accv[2][0] += xv.z * vv4.x; accv[2][1] += xv.z * vv4.y; accv[2][2] += xv.z * vv4.z; accv[2][3] += xv.z * vv4.w;
            accv[3][0] += xv.w * vv4.x; accv[3][1] += xv.w * vv4.y; accv[3][2] += xv.w * vv4.z; accv[3][3] += xv.w * vv4.w;
        }
        __syncthreads();
    }
#pragma unroll
    for (int i = 0; i < 4; i++) {
        size_t base = ((size_t)b * SK_ + s0 + tx * 4 + i) * C_ + o0 + ty * 4;
        *reinterpret_cast<float4*>(g_k + base) =
            make_float4(acck[i][0], acck[i][1], acck[i][2], acck[i][3]);
        *reinterpret_cast<float4*>(g_v + base) =
            make_float4(accv[i][0], accv[i][1], accv[i][2], accv[i][3]);
    }
}

// ---------------------------------------------------------------------------
// GEMM B (final projection): out[b][o][s] = sum_c W[o][c] * g_att[b][s][c]
// ---------------------------------------------------------------------------
__global__ __launch_bounds__(256)
void gemm_out_kernel(const float* __restrict__ W, float* __restrict__ Y) {
    int b  = blockIdx.z;
    int o0 = blockIdx.y * 64;
    int s0 = blockIdx.x * 64;
    int tx = threadIdx.x;          // s
    int ty = threadIdx.y;          // o
    int tid = ty * 16 + tx;

    __shared__ float As[16][68];   // [k][s]
    __shared__ float Wt[16][68];   // [k][o]

    float acc[4][4];
#pragma unroll
    for (int i = 0; i < 4; i++)
#pragma unroll
        for (int j = 0; j < 4; j++) acc[i][j] = 0.f;

    for (int kc = 0; kc < C_; kc += 16) {
        int row = tid >> 2;
        int col = (tid & 3) * 4;
        {
            float4 av = *reinterpret_cast<const float4*>(
                g_att + ((size_t)b * SQ_ + s0 + row) * C_ + kc + col);
            As[col + 0][row] = av.x; As[col + 1][row] = av.y;
            As[col + 2][row] = av.z; As[col + 3][row] = av.w;
        }
        {
            float4 wv = *reinterpret_cast<const float4*>(
                W + (size_t)(o0 + row) * C_ + kc + col);
            Wt[col + 0][row] = wv.x; Wt[col + 1][row] = wv.y;
            Wt[col + 2][row] = wv.z; Wt[col + 3][row] = wv.w;
        }
        __syncthreads();
#pragma unroll
        for (int kk = 0; kk < 16; kk++) {
            float4 xv = *reinterpret_cast<const float4*>(&As[kk][tx * 4]);
            float4 wv = *reinterpret_cast<const float4*>(&Wt[kk][ty * 4]);
            acc[0][0] += xv.x * wv.x; acc[0][1] += xv.x * wv.y; acc[0][2] += xv.x * wv.z; acc[0][3] += xv.x * wv.w;
            acc[1][0] += xv.y * wv.x; acc[1][1] += xv.y * wv.y; acc[1][2] += xv.y * wv.z; acc[1][3] += xv.y * wv.w;
            acc[2][0] += xv.z * wv.x; acc[2][1] += xv.z * wv.y; acc[2][2] += xv.z * wv.z; acc[2][3] += xv.z * wv.w;
            acc[3][0] += xv.w * wv.x; acc[3][1] += xv.w * wv.y; acc[3][2] += xv.w * wv.z; acc[3][3] += xv.w * wv.w;
        }
        __syncthreads();
    }
#pragma unroll
    for (int j = 0; j < 4; j++) {
        float4 o4 = make_float4(acc[0][j], acc[1][j], acc[2][j], acc[3][j]);
        *reinterpret_cast<float4*>(
            Y + ((size_t)b * C_ + o0 + ty * 4 + j) * SQ_ + s0 + tx * 4) = o4;
    }
}

// ---------------------------------------------------------------------------
// 3x3 SAME conv as implicit GEMM + fused coordinate epilogue.
// off(64oc, s) = W(64, 2304) x im2col(2304, s); then the epilogue converts
// each offset logit directly into the final kv-pixel-space sample coordinate:
//   f = ((base + tanh(val)*0.25) + 1) * 16 - 0.5
// where base is the x or y normalized base-grid coord (channel parity = comp).
// Channel layout oc = head*8 + p*2 + comp, pixel known from (blockIdx.x, tx, i).
// ---------------------------------------------------------------------------
__global__ __launch_bounds__(256)
void conv_off_gemm_kernel(const float* __restrict__ X, const float* __restrict__ W,
                          const float* __restrict__ bias) {
    int b  = blockIdx.y;
    int y  = blockIdx.x;           // image row = s-tile of 64 pixels
    int tx = threadIdx.x;          // 0..15 -> s (x position groups)
    int ty = threadIdx.y;          // 0..15 -> oc
    int tid = ty * 16 + tx;

    __shared__ float Xs[16][64];   // [k][x]
    __shared__ float Wt[16][68];   // [k][oc]

    float acc[4][4];
#pragma unroll
    for (int i = 0; i < 4; i++)
#pragma unroll
        for (int j = 0; j < 4; j++) acc[i][j] = 0.f;

    for (int kc = 0; kc < KC_; kc += 16) {
        {   // gather im2col tile: 16 K-rows x 64 x-positions
            int kk   = tid >> 4;            // 0..15
            int xc   = (tid & 15) * 4;      // 0,4,...,60
            int kidx = kc + kk;
            int c    = kidx / 9;
            int r9   = kidx - c * 9;
            int ky   = r9 / 3 - 1;          // -1,0,1
            int kx   = r9 - (r9 / 3) * 3 - 1;
            int gy   = y + ky;
            float v0 = 0.f, v1 = 0.f, v2 = 0.f, v3 = 0.f;
            if (gy >= 0 && gy < 64) {
                const float* rowp = X + (((size_t)b * C_ + c) * 64 + gy) * 64;
                int g0 = xc + 0 + kx, g1 = xc + 1 + kx, g2 = xc + 2 + kx, g3 = xc + 3 + kx;
                if (g0 >= 0 && g0 < 64) v0 = rowp[g0];
                if (g1 >= 0 && g1 < 64) v1 = rowp[g1];
                if (g2 >= 0 && g2 < 64) v2 = rowp[g2];
                if (g3 >= 0 && g3 < 64) v3 = rowp[g3];
            }
            Xs[kk][xc + 0] = v0; Xs[kk][xc + 1] = v1;
            Xs[kk][xc + 2] = v2; Xs[kk][xc + 3] = v3;
        }
        {   // load W tile (oc-major in gmem, contiguous k) -> k-major smem
            int row = tid >> 2;            // oc
            int col = (tid & 3) * 4;       // k
            float4 wv = *reinterpret_cast<const float4*>(
                W + (size_t)row * KC_ + kc + col);
            Wt[col + 0][row] = wv.x;
            Wt[col + 1][row] = wv.y;
            Wt[col + 2][row] = wv.z;
            Wt[col + 3][row] = wv.w;
        }
        __syncthreads();
#pragma unroll
        for (int kk = 0; kk < 16; kk++) {
            float4 xv = *reinterpret_cast<const float4*>(&Xs[kk][tx * 4]);
            float4 wv = *reinterpret_cast<const float4*>(&Wt[kk][ty * 4]);
            acc[0][0] += xv.x * wv.x; acc[0][1] += xv.x * wv.y; acc[0][2] += xv.x * wv.z; acc[0][3] += xv.x * wv.w;
            acc[1][0] += xv.y * wv.x; acc[1][1] += xv.y * wv.y; acc[1][2] += xv.y * wv.z; acc[1][3] += xv.y * wv.w;
            acc[2][0] += xv.z * wv.x; acc[2][1] += xv.z * wv.y; acc[2][2] += xv.z * wv.z; acc[2][3] += xv.z * wv.w;
            acc[3][0] += xv.w * wv.x; acc[3][1] += xv.w * wv.y; acc[3][2] += xv.w * wv.z; acc[3][3] += xv.w * wv.w;
        }
        __syncthreads();
    }

    // Epilogue: coordinate transform + store channel-last.
    // oc = ty*4 + j; ty*4 is even so (j & 1) == component (0=x, 1=y).
    float b0 = bias[ty * 4 + 0];
    float b1 = bias[ty * 4 + 1];
    float b2 = bias[ty * 4 + 2];
    float b3 = bias[ty * 4 + 3];
    float ybase = (2.f * (float)y - 63.f) * (1.f / 63.f);   // normalized y of this row
#pragma unroll
    for (int i = 0; i < 4; i++) {
        int pxi = tx * 4 + i;
        float xbase = (2.f * (float)pxi - 63.f) * (1.f / 63.f);
        int s = y * 64 + pxi;
        // comp pattern over j = 0,1,2,3 is x,y,x,y
        float fx0 = (xbase + tanhf(acc[i][0] + b0) * 0.25f + 1.f) * 16.f - 0.5f;
        float fy0 = (ybase + tanhf(acc[i][1] + b1) * 0.25f + 1.f) * 16.f - 0.5f;
        float fx1 = (xbase + tanhf(acc[i][2] + b2) * 0.25f + 1.f) * 16.f - 0.5f;
        float fy1 = (ybase + tanhf(acc[i][3] + b3) * 0.25f + 1.f) * 16.f - 0.5f;
        float4 o4 = make_float4(fx0, fy0, fx1, fy1);
        *reinterpret_cast<float4*>(
            &g_off[0] + ((size_t)b * SQ_ + s) * OC_ + ty * 4) = o4;
    }
}

// ---------------------------------------------------------------------------
// Deformable attention: one warp per (n = b*8+head, pixel). lane = channel d.
// g_off now holds final sample coords in kv pixel space; no tanh/grid math here.
// ---------------------------------------------------------------------------
__global__ __launch_bounds__(256)
void attn_kernel() {
    int warp = threadIdx.x >> 5;
    int lane = threadIdx.x & 31;
    int n = blockIdx.y;                 // 0..63
    int s = blockIdx.x * 8 + warp;      // 0..4095
    int b = n >> 3, head = n & 7;

    float qd = g_q[((size_t)b * SQ_ + s) * C_ + head * D_ + lane];
    const float* offp = &g_off[((size_t)b * SQ_ + s) * OC_ + head * (NP_ * 2)];
    const float* kb = &g_k[(size_t)b * SK_ * C_ + head * D_ + lane];
    const float* vb = &g_v[(size_t)b * SK_ * C_ + head * D_ + lane];

    float logit[NP_];
    int   tidx[NP_][4];
    float twgt[NP_][4];

#pragma unroll
    for (int p = 0; p < NP_; p++) {
        float fx = offp[2 * p + 0];
        float fy = offp[2 * p + 1];
        float x0 = floorf(fx), y0 = floorf(fy);
        float wx1 = fx - x0, wy1 = fy - y0;
        int x0i = (int)x0, y0i = (int)y0;

        float ks = 0.f;
#pragma unroll
        for (int t = 0; t < 4; t++) {
            int dy = t >> 1, dx = t & 1;
            int xi = x0i + dx, yi = y0i + dy;
            bool valid = (xi >= 0) && (xi < 32) && (yi >= 0) && (yi < 32);
            float wgt = (dx ? wx1 : 1.f - wx1) * (dy ? wy1 : 1.f - wy1);
            tidx[p][t] = valid ? (yi * 32 + xi) : -1;
            twgt[p][t] = valid ? wgt : 0.f;
            if (valid) ks += wgt * kb[(size_t)(yi * 32 + xi) * C_];
        }
        float dot = qd * ks;
#pragma unroll
        for (int o = 16; o > 0; o >>= 1)
            dot += __shfl_xor_sync(0xffffffffu, dot, o);
        logit[p] = dot * 0.17677669529663687f;  // 1/sqrt(32)
    }

    float m = fmaxf(fmaxf(logit[0], logit[1]), fmaxf(logit[2], logit[3]));
    float e0 = expf(logit[0] - m);
    float e1 = expf(logit[1] - m);
    float e2 = expf(logit[2] - m);
    float e3 = expf(logit[3] - m);
    float inv = 1.f / (e0 + e1 + e2 + e3);
    float a[NP_] = {e0 * inv, e1 * inv, e2 * inv, e3 * inv};

    float od = 0.f;
#pragma unroll
    for (int p = 0; p < NP_; p++)
#pragma unroll
        for (int t = 0; t < 4; t++)
            if (tidx[p][t] >= 0)
                od += a[p] * twgt[p][t] * vb[(size_t)tidx[p][t] * C_];

    g_att[((size_t)b * SQ_ + s) * C_ + head * D_ + lane] = od;
}

// ---------------------------------------------------------------------------
// Launch
// ---------------------------------------------------------------------------
extern "C" void kernel_launch(void* const* d_in, const int* in_sizes, int n_in,
                              void* d_out, int out_size) {
    const float* query = (const float*)d_in[0];
    const float* kv    = (const float*)d_in[1];
    const float* q_w   = (const float*)d_in[2];
    const float* k_w   = (const float*)d_in[3];
    const float* v_w   = (const float*)d_in[4];
    const float* off_w = (const float*)d_in[5];
    const float* off_b = (const float*)d_in[6];
    const float* out_w = (const float*)d_in[7];
    float* out = (float*)d_out;

    dim3 blk16(16, 16);

    // projections (channel-last outputs)
    gemm_q_kernel <<<dim3(SQ_ / 64, C_ / 64, B_), blk16>>>(query, q_w);
    gemm_kv_kernel<<<dim3(SK_ / 64, C_ / 64, B_), blk16>>>(kv, k_w, v_w);

    // offset conv 3x3 as implicit GEMM + coord epilogue
    conv_off_gemm_kernel<<<dim3(64, B_), blk16>>>(query, off_w, off_b);

    // deformable attention
    attn_kernel<<<dim3(SQ_ / 8, B_ * NH_), 256>>>();

    // final projection to (B, C, H, W)
    gemm_out_kernel<<<dim3(SQ_ / 64, C_ / 64, B_), blk16>>>(out_w, out);
}